// round 14
// baseline (speedup 1.0000x reference)
#include <cuda_runtime.h>
#include <cuda_fp16.h>
#include <cstdint>

#define T_SEQ    512
#define BATCH    4096
#define IND      64
#define HID      128
#define MT       32            // batch rows per CTA
#define NCTA     (BATCH / MT)  // 128
#define NKT      12            // k-tiles of 16 (K = 192); kt 0-3 = x, kt 4-11 = h
#define NTHREADS 256           // 8 warps: 2 row-tiles x 4 col-groups (n=32/warp)
#define BUFU32   (2 * NKT * 128)   // u32 per A buffer

// ---------------------------------------------------------------------------

__device__ __forceinline__ uint32_t packh2(float a, float b) {
    __half2 h = __floats2half2_rn(a, b);
    return *reinterpret_cast<uint32_t*>(&h);
}

// D += A(16x16) * B(16x8)^T (row.col), fp16 in, fp32 accum
__device__ __forceinline__ void mma16(float* d, const uint32_t* a, uint32_t b0, uint32_t b1) {
    asm volatile(
        "mma.sync.aligned.m16n8k16.row.col.f32.f16.f16.f32 "
        "{%0,%1,%2,%3}, {%4,%5,%6,%7}, {%8,%9}, {%0,%1,%2,%3};"
        : "+f"(d[0]), "+f"(d[1]), "+f"(d[2]), "+f"(d[3])
        : "r"(a[0]), "r"(a[1]), "r"(a[2]), "r"(a[3]), "r"(b0), "r"(b1));
}

// fp32 HW tanh (final step only)
__device__ __forceinline__ float tanh_hw(float v) {
    float r;
    asm("tanh.approx.f32 %0, %1;" : "=f"(r) : "f"(v));
    return r;
}

// pack two fp32 -> half2 (lo=a, hi=b), then tanh.approx.f16x2: 1 cvt + 1 MUFU
__device__ __forceinline__ uint32_t tanh2(float a, float b) {
    uint32_t z, r;
    asm("cvt.rn.f16x2.f32 %0, %1, %2;" : "=r"(z) : "f"(b), "f"(a));  // hi=b, lo=a
    asm("tanh.approx.f16x2 %0, %1;" : "=r"(r) : "r"(z));
    return r;
}

// u32 index of the half-PAIR (k, k+1) for row (0..31), k even (0..191)
// inside one A buffer laid out as [rt][kt][lane][4 regs] (m16n8k16 A frag).
__device__ __forceinline__ int xidx(int row, int k) {
    int kt = k >> 4, kk = k & 15;
    int lane = ((row & 7) << 2) | ((kk >> 1) & 3);
    int reg  = ((kk >> 3) << 1) | ((row >> 3) & 1);
    return ((row >> 4) * NKT + kt) * 128 + (lane << 2) + reg;
}

// ---------------------------------------------------------------------------

__global__ void __launch_bounds__(NTHREADS, 1)
rnn_kernel(const float* __restrict__ x, const float* __restrict__ Wih,
           const float* __restrict__ bih, const float* __restrict__ Whh,
           const float* __restrict__ bhh, float* __restrict__ out) {
    __shared__ uint32_t afrag[2][BUFU32];   // ping-pong: buf[s&1] kt0-3 = x_s, kt4-11 = h_{s-1}

    const int tid = threadIdx.x;
    const int wid = tid >> 5;
    const int lid = tid & 31;
    const int rt  = wid >> 2;        // row tile (independent recurrence domain)
    const int cg  = wid & 3;         // col group: cols cg*32 .. +31
    const int b0  = blockIdx.x * MT;

    // ---- B fragments (weights, fp16) resident in registers ----
    uint32_t breg[4][NKT][2];
#pragma unroll
    for (int i = 0; i < 4; i++) {
        const int n = ((cg << 2) + i) * 8 + (lid >> 2);
        const float* wih_r = Wih + n * IND;
        const float* whh_r = Whh + n * HID;
#pragma unroll
        for (int kt = 0; kt < 4; kt++)
#pragma unroll
            for (int jb = 0; jb < 2; jb++) {
                int k = (kt << 4) + ((lid & 3) << 1) + (jb << 3);
                breg[i][kt][jb] = packh2(wih_r[k], wih_r[k + 1]);
            }
#pragma unroll
        for (int kt = 4; kt < NKT; kt++)
#pragma unroll
            for (int jb = 0; jb < 2; jb++) {
                int k = (kt << 4) + ((lid & 3) << 1) + (jb << 3) - IND;
                breg[i][kt][jb] = packh2(whh_r[k], whh_r[k + 1]);
            }
    }

    // bias pairs (accumulator init values): cols c0(i) = cg*32 + i*8 + (lid&3)*2
    float2 bb[4];
#pragma unroll
    for (int i = 0; i < 4; i++) {
        const int c0 = (cg << 5) + (i << 3) + ((lid & 3) << 1);
        bb[i].x = bih[c0]     + bhh[c0];
        bb[i].y = bih[c0 + 1] + bhh[c0 + 1];
    }

    // ---- init buffer 0: zeros (h_{-1}=0) + x_0 ----
    for (int i = tid; i < BUFU32; i += NTHREADS) afrag[0][i] = 0u;
    __syncthreads();

    // x scatter geometry, confined to this thread's rt domain
    const int xdl = tid & 127;
    int   xw0[2], xw1[2];
    const float* xptr[2];
#pragma unroll
    for (int j = 0; j < 2; j++) {
        int idx = rt * 256 + xdl + j * 128;
        int row = idx >> 4;
        int k0  = (idx & 15) << 2;
        xw0[j] = xidx(row, k0);
        xw1[j] = xidx(row, k0 + 2);
        xptr[j] = x + (size_t)(b0 + row) * IND + k0;
    }
#pragma unroll
    for (int j = 0; j < 2; j++) {
        float4 xv = *(const float4*)xptr[j];
        afrag[0][xw0[j]] = packh2(xv.x, xv.y);
        afrag[0][xw1[j]] = packh2(xv.z, xv.w);
    }
    __syncthreads();

    const int rbase = (rt << 4) + (lid >> 2);
    const int barid = 1 + rt;
    const int aoff  = rt * NKT * 128 + (lid << 2);

    // SPLIT accumulators: dlo takes kt 0-5 (pre-armed with bias), dhi takes
    // kt 6-11 (zero). 8 independent 6-deep HMMA chains instead of 4x12-deep.
    float dlo[4][4], dhi[4][4];
#pragma unroll
    for (int i = 0; i < 4; i++) {
        dlo[i][0] = bb[i].x; dlo[i][1] = bb[i].y;
        dlo[i][2] = bb[i].x; dlo[i][3] = bb[i].y;
        dhi[i][0] = 0.f; dhi[i][1] = 0.f; dhi[i][2] = 0.f; dhi[i][3] = 0.f;
    }

    for (int t = 0; t < T_SEQ; t++) {
        // prefetch x_{t+1} (hidden under MMA phase)
        float4 xv0, xv1;
        const bool pf = (t + 1 < T_SEQ);
        if (pf) {
            const size_t off = (size_t)(t + 1) * BATCH * IND;
            xv0 = *(const float4*)(xptr[0] + off);
            xv1 = *(const float4*)(xptr[1] + off);
        }

        // ---- MMA: D = bias + [x_t | h] @ [W_ih | W_hh]^T (12 fp16 k-tiles),
        // kt 0-5 -> dlo, kt 6-11 -> dhi (halved dependency depth) ----
        const uint32_t* ar = afrag[t & 1] + aoff;
#pragma unroll
        for (int kt = 0; kt < 6; kt++) {
            uint4 av = *(const uint4*)(ar + kt * 128);   // LDS.128, conflict-free
            mma16(dlo[0], (const uint32_t*)&av, breg[0][kt][0], breg[0][kt][1]);
            mma16(dlo[1], (const uint32_t*)&av, breg[1][kt][0], breg[1][kt][1]);
            mma16(dlo[2], (const uint32_t*)&av, breg[2][kt][0], breg[2][kt][1]);
            mma16(dlo[3], (const uint32_t*)&av, breg[3][kt][0], breg[3][kt][1]);
        }
#pragma unroll
        for (int kt = 6; kt < NKT; kt++) {
            uint4 av = *(const uint4*)(ar + kt * 128);
            mma16(dhi[0], (const uint32_t*)&av, breg[0][kt][0], breg[0][kt][1]);
            mma16(dhi[1], (const uint32_t*)&av, breg[1][kt][0], breg[1][kt][1]);
            mma16(dhi[2], (const uint32_t*)&av, breg[2][kt][0], breg[2][kt][1]);
            mma16(dhi[3], (const uint32_t*)&av, breg[3][kt][0], breg[3][kt][1]);
        }

        if (pf) {
            // ---- epilogue: merge partials + f16x2 tanh + STS h_t ----
            uint32_t* aw = afrag[(t + 1) & 1];
            uint32_t* hw = aw + aoff;
#pragma unroll
            for (int j = 0; j < 2; j++) {
                uint4 pk;
                pk.x = tanh2(dlo[2*j][0]   + dhi[2*j][0],   dlo[2*j][1]   + dhi[2*j][1]);
                pk.y = tanh2(dlo[2*j][2]   + dhi[2*j][2],   dlo[2*j][3]   + dhi[2*j][3]);
                pk.z = tanh2(dlo[2*j+1][0] + dhi[2*j+1][0], dlo[2*j+1][1] + dhi[2*j+1][1]);
                pk.w = tanh2(dlo[2*j+1][2] + dhi[2*j+1][2], dlo[2*j+1][3] + dhi[2*j+1][3]);
                *(uint4*)(hw + (4 + (cg << 1) + j) * 128) = pk;   // STS.128
            }
            // re-arm accumulators for step t+1 (independent of STS/barrier)
#pragma unroll
            for (int i = 0; i < 4; i++) {
                dlo[i][0] = bb[i].x; dlo[i][1] = bb[i].y;
                dlo[i][2] = bb[i].x; dlo[i][3] = bb[i].y;
                dhi[i][0] = 0.f; dhi[i][1] = 0.f; dhi[i][2] = 0.f; dhi[i][3] = 0.f;
            }
            // scatter x_{t+1} into the other buffer's kt0-3
            aw[xw0[0]] = packh2(xv0.x, xv0.y);
            aw[xw1[0]] = packh2(xv0.z, xv0.w);
            aw[xw0[1]] = packh2(xv1.x, xv1.y);
            aw[xw1[1]] = packh2(xv1.z, xv1.w);
            asm volatile("bar.sync %0, %1;" :: "r"(barid), "n"(128) : "memory");
        } else {
            // final step: h_T via fp32 tanh straight to gmem
#pragma unroll
            for (int i = 0; i < 4; i++) {
                const int c0 = (cg << 5) + (i << 3) + ((lid & 3) << 1);
                *(float2*)(out + (size_t)(b0 + rbase) * HID + c0)
                    = make_float2(tanh_hw(dlo[i][0] + dhi[i][0]),
                                  tanh_hw(dlo[i][1] + dhi[i][1]));
                *(float2*)(out + (size_t)(b0 + rbase + 8) * HID + c0)
                    = make_float2(tanh_hw(dlo[i][2] + dhi[i][2]),
                                  tanh_hw(dlo[i][3] + dhi[i][3]));
            }
        }
    }
}

// ---------------------------------------------------------------------------

extern "C" void kernel_launch(void* const* d_in, const int* in_sizes, int n_in,
                              void* d_out, int out_size) {
    const float* x   = (const float*)d_in[0];
    const float* Wih = (const float*)d_in[1];
    const float* bih = (const float*)d_in[2];
    const float* Whh = (const float*)d_in[3];
    const float* bhh = (const float*)d_in[4];
    float* out = (float*)d_out;

    rnn_kernel<<<NCTA, NTHREADS>>>(x, Wih, bih, Whh, bhh, out);
}

// round 17
// speedup vs baseline: 1.0561x; 1.0561x over previous
#include <cuda_runtime.h>
#include <cuda_fp16.h>
#include <cstdint>

#define T_SEQ    512
#define BATCH    4096
#define IND      64
#define HID      128
#define MT       32            // batch rows per CTA
#define NCTA     (BATCH / MT)  // 128
#define NKT      12            // k-tiles of 16 (K = 192); kt 0-3 = x, kt 4-11 = h
#define NTHREADS 256           // 8 warps: 2 row-tiles x 4 col-groups (n=32/warp)
#define BUFU32   (2 * NKT * 128)   // u32 per A buffer

// ---------------------------------------------------------------------------

__device__ __forceinline__ uint32_t packh2(float a, float b) {
    __half2 h = __floats2half2_rn(a, b);
    return *reinterpret_cast<uint32_t*>(&h);
}

// D += A(16x16) * B(16x8)^T (row.col), fp16 in, fp32 accum
__device__ __forceinline__ void mma16(float* d, const uint32_t* a, uint32_t b0, uint32_t b1) {
    asm volatile(
        "mma.sync.aligned.m16n8k16.row.col.f32.f16.f16.f32 "
        "{%0,%1,%2,%3}, {%4,%5,%6,%7}, {%8,%9}, {%0,%1,%2,%3};"
        : "+f"(d[0]), "+f"(d[1]), "+f"(d[2]), "+f"(d[3])
        : "r"(a[0]), "r"(a[1]), "r"(a[2]), "r"(a[3]), "r"(b0), "r"(b1));
}

// fp32 HW tanh (final step only)
__device__ __forceinline__ float tanh_hw(float v) {
    float r;
    asm("tanh.approx.f32 %0, %1;" : "=f"(r) : "f"(v));
    return r;
}

// pack two fp32 -> half2 (lo=a, hi=b), then tanh.approx.f16x2: 1 cvt + 1 MUFU
__device__ __forceinline__ uint32_t tanh2(float a, float b) {
    uint32_t z, r;
    asm("cvt.rn.f16x2.f32 %0, %1, %2;" : "=r"(z) : "f"(b), "f"(a));  // hi=b, lo=a
    asm("tanh.approx.f16x2 %0, %1;" : "=r"(r) : "r"(z));
    return r;
}

// u32 index of the half-PAIR (k, k+1) for row (0..31), k even (0..191)
// inside one A buffer laid out as [rt][kt][lane][4 regs] (m16n8k16 A frag).
__device__ __forceinline__ int xidx(int row, int k) {
    int kt = k >> 4, kk = k & 15;
    int lane = ((row & 7) << 2) | ((kk >> 1) & 3);
    int reg  = ((kk >> 3) << 1) | ((row >> 3) & 1);
    return ((row >> 4) * NKT + kt) * 128 + (lane << 2) + reg;
}

// ---------------------------------------------------------------------------

__global__ void __launch_bounds__(NTHREADS, 1)
rnn_kernel(const float* __restrict__ x, const float* __restrict__ Wih,
           const float* __restrict__ bih, const float* __restrict__ Whh,
           const float* __restrict__ bhh, float* __restrict__ out) {
    __shared__ uint32_t afrag[2][BUFU32];   // ping-pong: buf[s&1] kt0-3 = x_s, kt4-11 = h_{s-1}

    const int tid = threadIdx.x;
    const int wid = tid >> 5;
    const int lid = tid & 31;
    const int rt  = wid >> 2;        // row tile (independent recurrence domain)
    const int cg  = wid & 3;         // col group: cols cg*32 .. +31
    const int b0  = blockIdx.x * MT;

    // ---- B fragments (fp16) resident in registers ----
    // bregx[i][kt]: x part, physical kt 0..3 (W_ih).
    // bregh[i][l]:  h part, logical l 0..7 -> PHYSICAL slab p = (2cg+2+l)&7
    //               (per-warp rotation puts this warp's OWN slabs at l=6,7 so
    //                every register index in the main loop is compile-time).
    uint32_t bregx[4][4][2];
    uint32_t bregh[4][8][2];
#pragma unroll
    for (int i = 0; i < 4; i++) {
        const int n = ((cg << 2) + i) * 8 + (lid >> 2);
        const float* wih_r = Wih + n * IND;
        const float* whh_r = Whh + n * HID;
#pragma unroll
        for (int kt = 0; kt < 4; kt++)
#pragma unroll
            for (int jb = 0; jb < 2; jb++) {
                int k = (kt << 4) + ((lid & 3) << 1) + (jb << 3);
                bregx[i][kt][jb] = packh2(wih_r[k], wih_r[k + 1]);
            }
#pragma unroll
        for (int l = 0; l < 8; l++) {
            int p = ((cg << 1) + 2 + l) & 7;
#pragma unroll
            for (int jb = 0; jb < 2; jb++) {
                int k = (p << 4) + ((lid & 3) << 1) + (jb << 3);
                bregh[i][l][jb] = packh2(whh_r[k], whh_r[k + 1]);
            }
        }
    }

    // bias pairs (accumulator init values): cols c0(i) = cg*32 + i*8 + (lid&3)*2
    float2 bb[4];
#pragma unroll
    for (int i = 0; i < 4; i++) {
        const int c0 = (cg << 5) + (i << 3) + ((lid & 3) << 1);
        bb[i].x = bih[c0]     + bhh[c0];
        bb[i].y = bih[c0 + 1] + bhh[c0 + 1];
    }

    // ---- init buffer 0: zeros (h_{-1}=0) + x_0 ----
    for (int i = tid; i < BUFU32; i += NTHREADS) afrag[0][i] = 0u;
    __syncthreads();

    // x scatter geometry, confined to this thread's rt domain
    const int xdl = tid & 127;
    int   xw0[2], xw1[2];
    const float* xptr[2];
#pragma unroll
    for (int j = 0; j < 2; j++) {
        int idx = rt * 256 + xdl + j * 128;
        int row = idx >> 4;
        int k0  = (idx & 15) << 2;
        xw0[j] = xidx(row, k0);
        xw1[j] = xidx(row, k0 + 2);
        xptr[j] = x + (size_t)(b0 + row) * IND + k0;
    }
#pragma unroll
    for (int j = 0; j < 2; j++) {
        float4 xv = *(const float4*)xptr[j];
        afrag[0][xw0[j]] = packh2(xv.x, xv.y);
        afrag[0][xw1[j]] = packh2(xv.z, xv.w);
    }
    __syncthreads();

    const int rbase = (rt << 4) + (lid >> 2);
    const int barid = 1 + rt;
    const int aoff  = rt * NKT * 128 + (lid << 2);

    // foreign-slab LDS offsets (logical l = 0..5), own-slab STS offsets
    int foff[6];
#pragma unroll
    for (int l = 0; l < 6; l++)
        foff[l] = (rt * NKT + 4 + (((cg << 1) + 2 + l) & 7)) * 128 + (lid << 2);
    const int ooff0 = (rt * NKT + 4 + (cg << 1)) * 128 + (lid << 2);
    const int ooff1 = ooff0 + 128;

    // pk = this warp's own h fragments (persist across steps; h_{-1} = 0)
    uint4 pk0 = make_uint4(0u, 0u, 0u, 0u);
    uint4 pk1 = make_uint4(0u, 0u, 0u, 0u);

    // accumulators pre-armed with bias (off the post-barrier chain)
    float d[4][4];
#pragma unroll
    for (int i = 0; i < 4; i++) {
        d[i][0] = bb[i].x; d[i][1] = bb[i].y;
        d[i][2] = bb[i].x; d[i][3] = bb[i].y;
    }

    for (int t = 0; t < T_SEQ; t++) {
        // prefetch x_{t+1} (hidden under MMA phase)
        float4 xv0, xv1;
        const bool pf = (t + 1 < T_SEQ);
        if (pf) {
            const size_t off = (size_t)(t + 1) * BATCH * IND;
            xv0 = *(const float4*)(xptr[0] + off);
            xv1 = *(const float4*)(xptr[1] + off);
        }

        const uint32_t* bufA = afrag[t & 1];

        // ---- issue the 6 foreign h-slab loads immediately at barrier exit ----
        uint4 fh[6];
#pragma unroll
        for (int l = 0; l < 6; l++) fh[l] = *(const uint4*)(bufA + foff[l]);

        // ---- own-slab MMAs from registers (no LDS dependency; covers LDS lat) ----
        mma16(d[0], (const uint32_t*)&pk0, bregh[0][6][0], bregh[0][6][1]);
        mma16(d[1], (const uint32_t*)&pk0, bregh[1][6][0], bregh[1][6][1]);
        mma16(d[2], (const uint32_t*)&pk0, bregh[2][6][0], bregh[2][6][1]);
        mma16(d[3], (const uint32_t*)&pk0, bregh[3][6][0], bregh[3][6][1]);
        mma16(d[0], (const uint32_t*)&pk1, bregh[0][7][0], bregh[0][7][1]);
        mma16(d[1], (const uint32_t*)&pk1, bregh[1][7][0], bregh[1][7][1]);
        mma16(d[2], (const uint32_t*)&pk1, bregh[2][7][0], bregh[2][7][1]);
        mma16(d[3], (const uint32_t*)&pk1, bregh[3][7][0], bregh[3][7][1]);

        // ---- x-tile loads (consumed last -> latency hidden by h MMAs) ----
        uint4 xf[4];
#pragma unroll
        for (int kt = 0; kt < 4; kt++) xf[kt] = *(const uint4*)(bufA + aoff + kt * 128);

        // ---- foreign h MMAs ----
#pragma unroll
        for (int l = 0; l < 6; l++) {
            mma16(d[0], (const uint32_t*)&fh[l], bregh[0][l][0], bregh[0][l][1]);
            mma16(d[1], (const uint32_t*)&fh[l], bregh[1][l][0], bregh[1][l][1]);
            mma16(d[2], (const uint32_t*)&fh[l], bregh[2][l][0], bregh[2][l][1]);
            mma16(d[3], (const uint32_t*)&fh[l], bregh[3][l][0], bregh[3][l][1]);
        }
        // ---- x MMAs ----
#pragma unroll
        for (int kt = 0; kt < 4; kt++) {
            mma16(d[0], (const uint32_t*)&xf[kt], bregx[0][kt][0], bregx[0][kt][1]);
            mma16(d[1], (const uint32_t*)&xf[kt], bregx[1][kt][0], bregx[1][kt][1]);
            mma16(d[2], (const uint32_t*)&xf[kt], bregx[2][kt][0], bregx[2][kt][1]);
            mma16(d[3], (const uint32_t*)&xf[kt], bregx[3][kt][0], bregx[3][kt][1]);
        }

        if (pf) {
            // ---- epilogue: f16x2 tanh -> pk (kept for next step) + STS h_t ----
            uint32_t* aw = afrag[(t + 1) & 1];
            pk0.x = tanh2(d[0][0], d[0][1]);
            pk0.y = tanh2(d[0][2], d[0][3]);
            pk0.z = tanh2(d[1][0], d[1][1]);
            pk0.w = tanh2(d[1][2], d[1][3]);
            *(uint4*)(aw + ooff0) = pk0;               // STS.128
            pk1.x = tanh2(d[2][0], d[2][1]);
            pk1.y = tanh2(d[2][2], d[2][3]);
            pk1.z = tanh2(d[3][0], d[3][1]);
            pk1.w = tanh2(d[3][2], d[3][3]);
            *(uint4*)(aw + ooff1) = pk1;               // STS.128
            // re-arm accumulators for step t+1 (independent of STS/barrier)
#pragma unroll
            for (int i = 0; i < 4; i++) {
                d[i][0] = bb[i].x; d[i][1] = bb[i].y;
                d[i][2] = bb[i].x; d[i][3] = bb[i].y;
            }
            // scatter x_{t+1} into the other buffer's kt0-3
            aw[xw0[0]] = packh2(xv0.x, xv0.y);
            aw[xw1[0]] = packh2(xv0.z, xv0.w);
            aw[xw0[1]] = packh2(xv1.x, xv1.y);
            aw[xw1[1]] = packh2(xv1.z, xv1.w);
            asm volatile("bar.sync %0, %1;" :: "r"(barid), "n"(128) : "memory");
        } else {
            // final step: h_T via fp32 tanh straight to gmem
#pragma unroll
            for (int i = 0; i < 4; i++) {
                const int c0 = (cg << 5) + (i << 3) + ((lid & 3) << 1);
                *(float2*)(out + (size_t)(b0 + rbase) * HID + c0)
                    = make_float2(tanh_hw(d[i][0]), tanh_hw(d[i][1]));
                *(float2*)(out + (size_t)(b0 + rbase + 8) * HID + c0)
                    = make_float2(tanh_hw(d[i][2]), tanh_hw(d[i][3]));
            }
        }
    }
}

// ---------------------------------------------------------------------------

extern "C" void kernel_launch(void* const* d_in, const int* in_sizes, int n_in,
                              void* d_out, int out_size) {
    const float* x   = (const float*)d_in[0];
    const float* Wih = (const float*)d_in[1];
    const float* bih = (const float*)d_in[2];
    const float* Whh = (const float*)d_in[3];
    const float* bhh = (const float*)d_in[4];
    float* out = (float*)d_out;

    rnn_kernel<<<NCTA, NTHREADS>>>(x, Wih, bih, Whh, bhh, out);
}